// round 2
// baseline (speedup 1.0000x reference)
#include <cuda_runtime.h>

// Problem constants
#define BATCH     16
#define WIDTH     262144
#define FLEN      32
#define WOUT      (WIDTH - FLEN + 1)      // 262113
#define TPB       256
#define OPT       8                       // outputs per thread
#define TILE_OUT  (TPB * OPT)             // 2048
#define TILE_IN   (TILE_OUT + FLEN - 1)   // 2079
#define NTILES    ((WOUT + TILE_OUT - 1) / TILE_OUT)  // 128
#define SCALEF    0.1778279410038923f     // sqrt(10^-1.5)

// Padded shared index: stride-9 effective lane stride -> conflict-free for
// thread base = tid*8 access patterns (9 coprime with 32 banks).
__device__ __forceinline__ int shidx(int i) { return i + (i >> 3); }
#define SH_SZ (TILE_IN + (TILE_IN >> 3) + 8)   // ~2344

// Accurate-enough fast tanh: 1 - 2/(exp(2x)+1).
// __expf -> FMUL+MUFU.EX2, __fdividef -> MUFU.RCP. rel err ~1e-6.
__device__ __forceinline__ float tanh_fast(float x) {
    float e = __expf(2.0f * x);
    return 1.0f - __fdividef(2.0f, e + 1.0f);
}

__global__ __launch_bounds__(TPB, 2)
void hammer_wiener_kernel(
    const float* __restrict__ xr_g, const float* __restrict__ xi_g,
    const float* __restrict__ w1pre_g, const float* __restrict__ w2pre_g,
    const float* __restrict__ wfr_g,   const float* __restrict__ wfi_g,
    const float* __restrict__ w1po_g,  const float* __restrict__ b1po_g,
    const float* __restrict__ w2po_g,  const float* __restrict__ b2po_g,
    float2* __restrict__ out)
{
    __shared__ float sh_r[SH_SZ];
    __shared__ float sh_i[SH_SZ];
    __shared__ float swr[FLEN], swi[FLEN];
    __shared__ float sw1[8], sw2[8], sw1p[8], sb1p[8], sw2p[8];
    __shared__ float sb2;

    const int tid  = threadIdx.x;
    const int tile = blockIdx.x;
    const int b    = blockIdx.y;
    const int t0   = tile * TILE_OUT;

    // ---- stage weights into shared ----
    if (tid < FLEN) {
        swr[tid] = wfr_g[tid];
        swi[tid] = wfi_g[tid];
    } else if (tid < FLEN + 8) {
        int f = tid - FLEN;
        sw1[f]  = w1pre_g[f];
        sw2[f]  = w2pre_g[f];
        sw1p[f] = w1po_g[f];
        sb1p[f] = b1po_g[f];
        sw2p[f] = w2po_g[f];
        if (f == 0) sb2 = b2po_g[0];
    }
    __syncthreads();

    // ---- pre-stage: magnitude MLP + phase rotation -> xh into shared ----
    {
        const float* xr_row = xr_g + (size_t)b * WIDTH + t0;
        const float* xi_row = xi_g + (size_t)b * WIDTH + t0;
        float cw1[8], cw2[8];
        #pragma unroll
        for (int f = 0; f < 8; f++) { cw1[f] = sw1[f]; cw2[f] = sw2[f]; }

        for (int i = tid; i < TILE_IN; i += TPB) {
            const int gi = t0 + i;
            float xr = 0.0f, xi = 0.0f;
            if (gi < WIDTH) { xr = xr_row[i]; xi = xi_row[i]; }
            float s   = fmaf(xr, xr, xi * xi);
            float inv = (s > 0.0f) ? rsqrtf(s) : 0.0f;
            float mag = s * inv;                 // |x|; 0 when s==0
            float m = 0.0f;
            #pragma unroll
            for (int f = 0; f < 8; f++) {
                float t = tanh_fast(mag * cw1[f]);
                m = fmaf(t, cw2[f], m);
            }
            // cos(phase)=xr*inv, sin(phase)=xi*inv ; when s==0, m==0 so xh==0
            const int si = shidx(i);
            sh_r[si] = m * (xr * inv);
            sh_i[si] = m * (xi * inv);
        }
    }
    __syncthreads();

    // ---- FIR weights into registers ----
    float rwr[FLEN], rwi[FLEN];
    #pragma unroll
    for (int l = 0; l < FLEN; l++) { rwr[l] = swr[l]; rwi[l] = swi[l]; }

    // ---- complex FIR: j-sweep over window, 8 contiguous outputs/thread ----
    float ar[OPT], ai[OPT];
    #pragma unroll
    for (int o = 0; o < OPT; o++) { ar[o] = 0.0f; ai[o] = 0.0f; }

    const int sbase = 9 * tid;  // shidx(tid*8) since tid*8 is a multiple of 8
    #pragma unroll
    for (int j = 0; j < OPT + FLEN - 1; j++) {
        const int si = sbase + j + (j >> 3);
        const float xr = sh_r[si];
        const float xi = sh_i[si];
        #pragma unroll
        for (int o = 0; o < OPT; o++) {
            const int l = j - o;
            if (l >= 0 && l < FLEN) {
                ar[o] = fmaf(xr,  rwr[l], ar[o]);
                ar[o] = fmaf(-xi, rwi[l], ar[o]);
                ai[o] = fmaf(xi,  rwr[l], ai[o]);
                ai[o] = fmaf(xr,  rwi[l], ai[o]);
            }
        }
    }

    // ---- post-stage MLP + rotation + store ----
    float cw1p[8], cb1p[8], cw2p[8];
    #pragma unroll
    for (int f = 0; f < 8; f++) { cw1p[f] = sw1p[f]; cb1p[f] = sb1p[f]; cw2p[f] = sw2p[f]; }
    const float cb2 = sb2;

    const int obase = t0 + tid * OPT;
    float2* orow = out + (size_t)b * WOUT + obase;
    #pragma unroll
    for (int o = 0; o < OPT; o++) {
        if (obase + o < WOUT) {
            const float zr = ar[o];
            const float zi = ai[o];
            float s    = fmaf(zr, zr, zi * zi);
            float inv  = (s > 0.0f) ? rsqrtf(s) : 0.0f;
            float zmag = s * inv;
            float cosz = (s > 0.0f) ? zr * inv : 1.0f;
            float sinz = zi * inv;
            float zm = cb2;
            #pragma unroll
            for (int f = 0; f < 8; f++) {
                float g = fmaf(zmag, cw1p[f], cb1p[f]);
                g = fmaxf(g, 0.0f);
                zm = fmaf(g, cw2p[f], zm);
            }
            orow[o] = make_float2(SCALEF * zm * cosz, SCALEF * zm * sinz);
        }
    }
}

extern "C" void kernel_launch(void* const* d_in, const int* in_sizes, int n_in,
                              void* d_out, int out_size)
{
    (void)in_sizes; (void)n_in; (void)out_size;
    const float* xr   = (const float*)d_in[0];
    const float* xi   = (const float*)d_in[1];
    const float* w1pr = (const float*)d_in[2];
    const float* w2pr = (const float*)d_in[3];
    const float* wfr  = (const float*)d_in[4];
    const float* wfi  = (const float*)d_in[5];
    const float* w1po = (const float*)d_in[6];
    const float* b1po = (const float*)d_in[7];
    const float* w2po = (const float*)d_in[8];
    const float* b2po = (const float*)d_in[9];

    dim3 grid(NTILES, BATCH);
    hammer_wiener_kernel<<<grid, TPB>>>(xr, xi, w1pr, w2pr, wfr, wfi,
                                        w1po, b1po, w2po, b2po,
                                        (float2*)d_out);
}

// round 3
// speedup vs baseline: 1.4383x; 1.4383x over previous
#include <cuda_runtime.h>

// Problem constants
#define BATCH     16
#define WIDTH     262144
#define FLEN      32
#define WOUT      (WIDTH - FLEN + 1)      // 262113
#define TPB       256
#define OPT       8                       // outputs per thread
#define TILE_OUT  (TPB * OPT)             // 2048
#define TILE_IN   (TILE_OUT + FLEN - 1)   // 2079
#define NTILES    ((WOUT + TILE_OUT - 1) / TILE_OUT)  // 128
#define SCALEF    0.1778279410038923f     // sqrt(10^-1.5)
#define CHUNKS    4
#define CT        (FLEN / CHUNKS)         // 8 taps per chunk

// Padded shared index on float2 granularity: i + (i>>3) -> per-lane stride of
// 9 float2 (72B) for base tid*8; 2 wavefronts per LDS.64 = the data-volume floor.
__device__ __forceinline__ int p2(int i) { return i + (i >> 3); }
#define SH2_SZ (TILE_IN + (TILE_IN >> 3) + 8)   // ~2347 float2 ≈ 18.8 KB

// ---- packed f32x2 helpers (ptxas will NOT auto-fuse; PTX-only path) ----
__device__ __forceinline__ unsigned long long pack2(float lo, float hi) {
    unsigned long long r;
    asm("mov.b64 %0, {%1,%2};" : "=l"(r) : "f"(lo), "f"(hi));
    return r;
}
__device__ __forceinline__ void unpack2(unsigned long long v, float& lo, float& hi) {
    asm("mov.b64 {%0,%1}, %2;" : "=f"(lo), "=f"(hi) : "l"(v));
}
__device__ __forceinline__ void ffma2(unsigned long long& c,
                                      unsigned long long a, unsigned long long b) {
    asm("fma.rn.f32x2 %0, %1, %2, %0;" : "+l"(c) : "l"(a), "l"(b));
}

// Single-MUFU tanh (sm_75+). abs err ~5e-4, diluted by downstream averaging.
__device__ __forceinline__ float tanh_mufu(float x) {
    float y;
    asm("tanh.approx.f32 %0, %1;" : "=f"(y) : "f"(x));
    return y;
}

__global__ __launch_bounds__(TPB, 3)
void hammer_wiener_kernel(
    const float* __restrict__ xr_g, const float* __restrict__ xi_g,
    const float* __restrict__ w1pre_g, const float* __restrict__ w2pre_g,
    const float* __restrict__ wfr_g,   const float* __restrict__ wfi_g,
    const float* __restrict__ w1po_g,  const float* __restrict__ b1po_g,
    const float* __restrict__ w2po_g,  const float* __restrict__ b2po_g,
    float2* __restrict__ out)
{
    __shared__ float2 shx[SH2_SZ];
    __shared__ float swr[FLEN], swi[FLEN];
    __shared__ float sw1[8], sw2[8], sw1p[8], sb1p[8], sw2p[8];
    __shared__ float sb2;

    const int tid  = threadIdx.x;
    const int tile = blockIdx.x;
    const int b    = blockIdx.y;
    const int t0   = tile * TILE_OUT;

    // ---- stage weights into shared ----
    if (tid < FLEN) {
        swr[tid] = wfr_g[tid];
        swi[tid] = wfi_g[tid];
    } else if (tid < FLEN + 8) {
        int f = tid - FLEN;
        sw1[f]  = w1pre_g[f];
        sw2[f]  = w2pre_g[f];
        sw1p[f] = w1po_g[f];
        sb1p[f] = b1po_g[f];
        sw2p[f] = w2po_g[f];
        if (f == 0) sb2 = b2po_g[0];
    }
    __syncthreads();

    // ---- pre-stage: |x| MLP (tanh) + phase rotation -> xh into shared ----
    {
        const float* xr_row = xr_g + (size_t)b * WIDTH + t0;
        const float* xi_row = xi_g + (size_t)b * WIDTH + t0;
        float cw1[8], cw2[8];
        #pragma unroll
        for (int f = 0; f < 8; f++) { cw1[f] = sw1[f]; cw2[f] = sw2[f]; }

        for (int i = tid; i < TILE_IN; i += TPB) {
            const int gi = t0 + i;
            float xr = 0.0f, xi = 0.0f;
            if (gi < WIDTH) { xr = xr_row[i]; xi = xi_row[i]; }
            float s   = fmaf(xr, xr, xi * xi);
            float inv = (s > 0.0f) ? rsqrtf(s) : 0.0f;
            float mag = s * inv;                   // |x|; 0 when s==0
            float m = 0.0f;
            #pragma unroll
            for (int f = 0; f < 8; f++) {
                float t = tanh_mufu(mag * cw1[f]);
                m = fmaf(t, cw2[f], m);
            }
            // cos(phase)=xr*inv, sin(phase)=xi*inv ; s==0 -> m==0 -> xh==0
            shx[p2(i)] = make_float2(m * (xr * inv), m * (xi * inv));
        }
    }
    __syncthreads();

    // ---- complex FIR with packed f32x2 accumulators, chunked weights ----
    unsigned long long acc[OPT];
    #pragma unroll
    for (int o = 0; o < OPT; o++) acc[o] = 0ull;

    #pragma unroll 1                      // keep one chunk's weights live (32 regs)
    for (int c = 0; c < CHUNKS; c++) {
        unsigned long long wrr[CT], wii[CT];
        #pragma unroll
        for (int k = 0; k < CT; k++) {
            float wr = swr[c * CT + k];
            float wi = swi[c * CT + k];
            wrr[k] = pack2(wr, wr);
            wii[k] = pack2(wi, wi);
        }
        // input index i = 8*tid + 8*c + jj ; padded: 9*(tid+c) + jj + (jj>>3)
        const int bb = 9 * (tid + c);
        #pragma unroll
        for (int jj = 0; jj < CT + OPT - 1; jj++) {   // 15 window positions
            const float2 x = shx[bb + jj + (jj >> 3)];
            const unsigned long long xp = pack2(x.x,  x.y);   // ( xr, xi)
            const unsigned long long xm = pack2(-x.y, x.x);   // (-xi, xr)
            #pragma unroll
            for (int o = 0; o < OPT; o++) {
                const int k = jj - o;
                if (k >= 0 && k < CT) {
                    ffma2(acc[o], xp, wrr[k]);   // (ar,ai) += (xr,xi)*(wr,wr)
                    ffma2(acc[o], xm, wii[k]);   // (ar,ai) += (-xi,xr)*(wi,wi)
                }
            }
        }
    }

    // ---- post-stage MLP (relu) + rotation + store ----
    float cw1p[8], cb1p[8], cw2p[8];
    #pragma unroll
    for (int f = 0; f < 8; f++) { cw1p[f] = sw1p[f]; cb1p[f] = sb1p[f]; cw2p[f] = sw2p[f]; }
    const float cb2 = sb2;

    const int obase = t0 + tid * OPT;
    float2* orow = out + (size_t)b * WOUT + obase;
    #pragma unroll
    for (int o = 0; o < OPT; o++) {
        if (obase + o < WOUT) {
            float zr, zi;
            unpack2(acc[o], zr, zi);
            float s    = fmaf(zr, zr, zi * zi);
            float inv  = (s > 0.0f) ? rsqrtf(s) : 0.0f;
            float zmag = s * inv;
            float cosz = (s > 0.0f) ? zr * inv : 1.0f;
            float sinz = zi * inv;
            float zm = cb2;
            #pragma unroll
            for (int f = 0; f < 8; f++) {
                float g = fmaf(zmag, cw1p[f], cb1p[f]);
                g = fmaxf(g, 0.0f);
                zm = fmaf(g, cw2p[f], zm);
            }
            orow[o] = make_float2(SCALEF * zm * cosz, SCALEF * zm * sinz);
        }
    }
}

extern "C" void kernel_launch(void* const* d_in, const int* in_sizes, int n_in,
                              void* d_out, int out_size)
{
    (void)in_sizes; (void)n_in; (void)out_size;
    const float* xr   = (const float*)d_in[0];
    const float* xi   = (const float*)d_in[1];
    const float* w1pr = (const float*)d_in[2];
    const float* w2pr = (const float*)d_in[3];
    const float* wfr  = (const float*)d_in[4];
    const float* wfi  = (const float*)d_in[5];
    const float* w1po = (const float*)d_in[6];
    const float* b1po = (const float*)d_in[7];
    const float* w2po = (const float*)d_in[8];
    const float* b2po = (const float*)d_in[9];

    dim3 grid(NTILES, BATCH);
    hammer_wiener_kernel<<<grid, TPB>>>(xr, xi, w1pr, w2pr, wfr, wfi,
                                        w1po, b1po, w2po, b2po,
                                        (float2*)d_out);
}

// round 5
// speedup vs baseline: 1.5220x; 1.0582x over previous
#include <cuda_runtime.h>

// Problem constants
#define BATCH     16
#define WIDTH     262144
#define FLEN      32
#define WOUT      (WIDTH - FLEN + 1)      // 262113
#define TPB       256
#define OPT       8                       // outputs per thread
#define TILE_OUT  (TPB * OPT)             // 2048
#define TILE_IN   (TILE_OUT + FLEN - 1)   // 2079
#define NTILES    ((WOUT + TILE_OUT - 1) / TILE_OUT)  // 128
#define SCALEF    0.1778279410038923f     // sqrt(10^-1.5)
#define CHUNKS    4
#define CT        (FLEN / CHUNKS)         // 8 taps per chunk

// Padded shared index at 16B (ulonglong2) granularity: lane stride for base
// tid*8 becomes 9 elements = 144B = 4 banks mod 32 -> each 8-lane phase of an
// LDS.128 covers disjoint 4-bank groups: conflict-free.
__device__ __forceinline__ int p2(int i) { return i + (i >> 3); }
#define SH_SZ (TILE_IN + (TILE_IN >> 3) + 8)   // 2346 elems * 16B = 37.5 KB

// ---- packed f32x2 helpers (PTX-only; ptxas won't auto-fuse) ----
__device__ __forceinline__ unsigned long long pack2(float lo, float hi) {
    unsigned long long r;
    asm("mov.b64 %0, {%1,%2};" : "=l"(r) : "f"(lo), "f"(hi));
    return r;
}
__device__ __forceinline__ void unpack2(unsigned long long v, float& lo, float& hi) {
    asm("mov.b64 {%0,%1}, %2;" : "=f"(lo), "=f"(hi) : "l"(v));
}
__device__ __forceinline__ void ffma2(unsigned long long& c,
                                      unsigned long long a, unsigned long long b) {
    asm("fma.rn.f32x2 %0, %1, %2, %0;" : "+l"(c) : "l"(a), "l"(b));
}

// Single-MUFU tanh (sm_75+).
__device__ __forceinline__ float tanh_mufu(float x) {
    float y;
    asm("tanh.approx.f32 %0, %1;" : "=f"(y) : "f"(x));
    return y;
}

__global__ __launch_bounds__(TPB, 4)
void hammer_wiener_kernel(
    const float* __restrict__ xr_g, const float* __restrict__ xi_g,
    const float* __restrict__ w1pre_g, const float* __restrict__ w2pre_g,
    const float* __restrict__ wfr_g,   const float* __restrict__ wfi_g,
    const float* __restrict__ w1po_g,  const float* __restrict__ b1po_g,
    const float* __restrict__ w2po_g,  const float* __restrict__ b2po_g,
    float2* __restrict__ out)
{
    // Each element holds { (xr,xi) , (-xi,xr) } pre-packed for the two FFMA2s.
    __shared__ ulonglong2 shx[SH_SZ];
    __shared__ float swr[FLEN], swi[FLEN];
    __shared__ float sw1[8], sw2[8], sw1p[8], sb1p[8], sw2p[8];
    __shared__ float sb2;

    const int tid  = threadIdx.x;
    const int tile = blockIdx.x;
    const int b    = blockIdx.y;
    const int t0   = tile * TILE_OUT;

    // ---- stage weights into shared ----
    if (tid < FLEN) {
        swr[tid] = wfr_g[tid];
        swi[tid] = wfi_g[tid];
    } else if (tid < FLEN + 8) {
        int f = tid - FLEN;
        sw1[f]  = w1pre_g[f];
        sw2[f]  = w2pre_g[f];
        sw1p[f] = w1po_g[f];
        sb1p[f] = b1po_g[f];
        sw2p[f] = w2po_g[f];
        if (f == 0) sb2 = b2po_g[0];
    }
    __syncthreads();

    // ---- pre-stage: |x| MLP (tanh) + rotation -> both packings into shared ----
    {
        const float* xr_row = xr_g + (size_t)b * WIDTH + t0;
        const float* xi_row = xi_g + (size_t)b * WIDTH + t0;
        float cw1[8], cw2[8];
        #pragma unroll
        for (int f = 0; f < 8; f++) { cw1[f] = sw1[f]; cw2[f] = sw2[f]; }

        // vector part: 2048 elems = 2 iters x 256 threads x float4 (aligned:
        // tile base is 8KB-aligned, never OOB since t0+2047 <= WIDTH-1).
        #pragma unroll
        for (int it = 0; it < 2; it++) {
            const int i = (it * TPB + tid) * 4;
            const float4 vr = *reinterpret_cast<const float4*>(xr_row + i);
            const float4 vi = *reinterpret_cast<const float4*>(xi_row + i);
            const float rr[4] = {vr.x, vr.y, vr.z, vr.w};
            const float ii[4] = {vi.x, vi.y, vi.z, vi.w};
            #pragma unroll
            for (int k = 0; k < 4; k++) {
                const float xr = rr[k], xi = ii[k];
                float s   = fmaf(xr, xr, xi * xi);
                float inv = (s > 0.0f) ? rsqrtf(s) : 0.0f;
                float mag = s * inv;
                float m = 0.0f;
                #pragma unroll
                for (int f = 0; f < 8; f++)
                    m = fmaf(tanh_mufu(mag * cw1[f]), cw2[f], m);
                const float hr = m * (xr * inv);
                const float hi = m * (xi * inv);
                ulonglong2 e;
                e.x = pack2(hr, hi);
                e.y = pack2(-hi, hr);
                shx[p2(i + k)] = e;
            }
        }
        // scalar halo: 31 elems, guard global bound (last tile overruns WIDTH)
        if (tid < TILE_IN - TILE_OUT) {
            const int i  = TILE_OUT + tid;
            const int gi = t0 + i;
            float xr = 0.0f, xi = 0.0f;
            if (gi < WIDTH) { xr = xr_row[i]; xi = xi_row[i]; }
            float s   = fmaf(xr, xr, xi * xi);
            float inv = (s > 0.0f) ? rsqrtf(s) : 0.0f;
            float mag = s * inv;
            float m = 0.0f;
            #pragma unroll
            for (int f = 0; f < 8; f++)
                m = fmaf(tanh_mufu(mag * cw1[f]), cw2[f], m);
            const float hr = m * (xr * inv);
            const float hi = m * (xi * inv);
            ulonglong2 e;
            e.x = pack2(hr, hi);
            e.y = pack2(-hi, hr);
            shx[p2(i)] = e;
        }
    }
    __syncthreads();

    // ---- complex FIR: packed f32x2 accumulators, chunked weights ----
    unsigned long long acc[OPT];
    #pragma unroll
    for (int o = 0; o < OPT; o++) acc[o] = 0ull;

    #pragma unroll 1                       // one chunk's weights live at a time
    for (int c = 0; c < CHUNKS; c++) {
        unsigned long long wrr[CT], wii[CT];
        #pragma unroll
        for (int k = 0; k < CT; k++) {
            float wr = swr[c * CT + k];
            float wi = swi[c * CT + k];
            wrr[k] = pack2(wr, wr);
            wii[k] = pack2(wi, wi);
        }
        // element index i = 8*tid + 8*c + jj ; padded: 9*(tid+c) + jj + (jj>>3)
        const int bb = 9 * (tid + c);
        #pragma unroll
        for (int jj = 0; jj < CT + OPT - 1; jj++) {   // 15 window positions
            const ulonglong2 x = shx[bb + jj + (jj >> 3)];  // LDS.128
            #pragma unroll
            for (int o = 0; o < OPT; o++) {
                const int k = jj - o;
                if (k >= 0 && k < CT) {
                    ffma2(acc[o], x.x, wrr[k]);   // (ar,ai) += ( xr,xi)*(wr,wr)
                    ffma2(acc[o], x.y, wii[k]);   // (ar,ai) += (-xi,xr)*(wi,wi)
                }
            }
        }
    }

    // ---- post-stage MLP (relu) + rotation + store ----
    float cw1p[8], cb1p[8], cw2p[8];
    #pragma unroll
    for (int f = 0; f < 8; f++) { cw1p[f] = sw1p[f]; cb1p[f] = sb1p[f]; cw2p[f] = sw2p[f]; }
    const float cb2 = sb2;

    const int obase = t0 + tid * OPT;
    float2* orow = out + (size_t)b * WOUT + obase;
    #pragma unroll
    for (int o = 0; o < OPT; o++) {
        if (obase + o < WOUT) {
            float zr, zi;
            unpack2(acc[o], zr, zi);
            float s    = fmaf(zr, zr, zi * zi);
            float inv  = (s > 0.0f) ? rsqrtf(s) : 0.0f;
            float zmag = s * inv;
            float cosz = (s > 0.0f) ? zr * inv : 1.0f;
            float sinz = zi * inv;
            float zm = cb2;
            #pragma unroll
            for (int f = 0; f < 8; f++) {
                float g = fmaf(zmag, cw1p[f], cb1p[f]);
                g = fmaxf(g, 0.0f);
                zm = fmaf(g, cw2p[f], zm);
            }
            orow[o] = make_float2(SCALEF * zm * cosz, SCALEF * zm * sinz);
        }
    }
}

extern "C" void kernel_launch(void* const* d_in, const int* in_sizes, int n_in,
                              void* d_out, int out_size)
{
    (void)in_sizes; (void)n_in; (void)out_size;
    const float* xr   = (const float*)d_in[0];
    const float* xi   = (const float*)d_in[1];
    const float* w1pr = (const float*)d_in[2];
    const float* w2pr = (const float*)d_in[3];
    const float* wfr  = (const float*)d_in[4];
    const float* wfi  = (const float*)d_in[5];
    const float* w1po = (const float*)d_in[6];
    const float* b1po = (const float*)d_in[7];
    const float* w2po = (const float*)d_in[8];
    const float* b2po = (const float*)d_in[9];

    dim3 grid(NTILES, BATCH);
    hammer_wiener_kernel<<<grid, TPB>>>(xr, xi, w1pr, w2pr, wfr, wfi,
                                        w1po, b1po, w2po, b2po,
                                        (float2*)d_out);
}

// round 6
// speedup vs baseline: 1.6590x; 1.0900x over previous
#include <cuda_runtime.h>

// Problem constants
#define BATCH     16
#define WIDTH     262144
#define FLEN      32
#define WOUT      (WIDTH - FLEN + 1)      // 262113
#define TPB       256
#define OPT       8                       // outputs per thread
#define TILE_OUT  (TPB * OPT)             // 2048
#define TILE_IN   (TILE_OUT + FLEN - 1)   // 2079
#define NTILES    ((WOUT + TILE_OUT - 1) / TILE_OUT)  // 128
#define SCALEF    0.1778279410038923f     // sqrt(10^-1.5)
#define CHUNKS    4
#define CT        (FLEN / CHUNKS)         // 8 taps per chunk
#define WIN       (CT + OPT - 1)          // 15-element sliding window

// Padded shared index at float2 (8B) granularity: base tid*8 -> lane stride
// 9 elems = 72B; bank = 18*l mod 32 distinct within each 16-lane LDS.64 phase
// -> conflict-free.
__device__ __forceinline__ int p2(int i) { return i + (i >> 3); }
#define SH_SZ (TILE_IN + (TILE_IN >> 3) + 8)   // ~2346 float2 = 18.8 KB

typedef unsigned long long ull;

// ---- packed f32x2 helpers (PTX-only; ptxas won't auto-fuse) ----
__device__ __forceinline__ ull pack2(float lo, float hi) {
    ull r;
    asm("mov.b64 %0, {%1,%2};" : "=l"(r) : "f"(lo), "f"(hi));
    return r;
}
__device__ __forceinline__ void unpack2(ull v, float& lo, float& hi) {
    asm("mov.b64 {%0,%1}, %2;" : "=f"(lo), "=f"(hi) : "l"(v));
}
__device__ __forceinline__ void ffma2(ull& c, ull a, ull b) {
    asm("fma.rn.f32x2 %0, %1, %2, %0;" : "+l"(c) : "l"(a), "l"(b));
}
__device__ __forceinline__ ull ld_sh2(const float2* p) {
    float2 v = *p;
    return pack2(v.x, v.y);
}

// Single-MUFU tanh (sm_75+).
__device__ __forceinline__ float tanh_mufu(float x) {
    float y;
    asm("tanh.approx.f32 %0, %1;" : "=f"(y) : "f"(x));
    return y;
}

__global__ __launch_bounds__(TPB, 4)
void hammer_wiener_kernel(
    const float* __restrict__ xr_g, const float* __restrict__ xi_g,
    const float* __restrict__ w1pre_g, const float* __restrict__ w2pre_g,
    const float* __restrict__ wfr_g,   const float* __restrict__ wfi_g,
    const float* __restrict__ w1po_g,  const float* __restrict__ b1po_g,
    const float* __restrict__ w2po_g,  const float* __restrict__ b2po_g,
    float2* __restrict__ out)
{
    __shared__ float2 shx[SH_SZ];                 // (xr, xi) only: 8B/elem
    __shared__ float swr[FLEN], swi[FLEN];
    __shared__ float sw1[8], sw2[8], sw1p[8], sb1p[8], sw2p[8];
    __shared__ float sb2;

    const int tid  = threadIdx.x;
    const int tile = blockIdx.x;
    const int b    = blockIdx.y;
    const int t0   = tile * TILE_OUT;

    // ---- stage weights into shared ----
    if (tid < FLEN) {
        swr[tid] = wfr_g[tid];
        swi[tid] = wfi_g[tid];
    } else if (tid < FLEN + 8) {
        int f = tid - FLEN;
        sw1[f]  = w1pre_g[f];
        sw2[f]  = w2pre_g[f];
        sw1p[f] = w1po_g[f];
        sb1p[f] = b1po_g[f];
        sw2p[f] = w2po_g[f];
        if (f == 0) sb2 = b2po_g[0];
    }
    __syncthreads();

    // ---- pre-stage: |x| MLP (tanh) + rotation -> (xr,xi) into shared ----
    {
        const float* xr_row = xr_g + (size_t)b * WIDTH + t0;
        const float* xi_row = xi_g + (size_t)b * WIDTH + t0;
        float cw1[8], cw2[8];
        #pragma unroll
        for (int f = 0; f < 8; f++) { cw1[f] = sw1[f]; cw2[f] = sw2[f]; }

        // vector part: 2048 elems = 2 iters x 256 threads x float4 (tile base
        // is 8KB-aligned; in-bounds since t0+2047 <= WIDTH-1)
        #pragma unroll
        for (int it = 0; it < 2; it++) {
            const int i = (it * TPB + tid) * 4;
            const float4 vr = *reinterpret_cast<const float4*>(xr_row + i);
            const float4 vi = *reinterpret_cast<const float4*>(xi_row + i);
            const float rr[4] = {vr.x, vr.y, vr.z, vr.w};
            const float ii[4] = {vi.x, vi.y, vi.z, vi.w};
            #pragma unroll
            for (int k = 0; k < 4; k++) {
                const float xr = rr[k], xi = ii[k];
                float s   = fmaf(xr, xr, xi * xi);
                float inv = (s > 0.0f) ? rsqrtf(s) : 0.0f;
                float mag = s * inv;
                float m = 0.0f;
                #pragma unroll
                for (int f = 0; f < 8; f++)
                    m = fmaf(tanh_mufu(mag * cw1[f]), cw2[f], m);
                shx[p2(i + k)] = make_float2(m * (xr * inv), m * (xi * inv));
            }
        }
        // scalar halo: 31 elems, guard global bound (last tile overruns WIDTH)
        if (tid < TILE_IN - TILE_OUT) {
            const int i  = TILE_OUT + tid;
            const int gi = t0 + i;
            float xr = 0.0f, xi = 0.0f;
            if (gi < WIDTH) { xr = xr_row[i]; xi = xi_row[i]; }
            float s   = fmaf(xr, xr, xi * xi);
            float inv = (s > 0.0f) ? rsqrtf(s) : 0.0f;
            float mag = s * inv;
            float m = 0.0f;
            #pragma unroll
            for (int f = 0; f < 8; f++)
                m = fmaf(tanh_mufu(mag * cw1[f]), cw2[f], m);
            shx[p2(i)] = make_float2(m * (xr * inv), m * (xi * inv));
        }
    }
    __syncthreads();

    // ---- complex FIR: dual packed accumulators, tap-major sliding window ----
    // accA[o] = (Σ xr·wr, Σ xi·wr) ; accB[o] = (Σ xr·wi, Σ xi·wi)
    ull accA[OPT], accB[OPT];
    #pragma unroll
    for (int o = 0; o < OPT; o++) { accA[o] = 0ull; accB[o] = 0ull; }

    #pragma unroll 1
    for (int c = 0; c < CHUNKS; c++) {
        // element index i = 8*(tid+c) + j ; padded: 9*(tid+c) + j + (j>>3)
        const int bb = 9 * (tid + c);
        ull xw[WIN];
        // preload window [0..8] (covers k=0 plus 1-ahead prefetch)
        #pragma unroll
        for (int j = 0; j < OPT + 1; j++)
            xw[j] = ld_sh2(&shx[bb + j + (j >> 3)]);

        #pragma unroll
        for (int k = 0; k < CT; k++) {
            // prefetch x for iteration k+2 (uses up to index (k+2)+7)
            if (k + OPT + 1 < WIN) {
                const int j = k + OPT + 1;
                xw[j] = ld_sh2(&shx[bb + j + (j >> 3)]);
            }
            const float wr = swr[c * CT + k];
            const float wi = swi[c * CT + k];
            const ull wrr = pack2(wr, wr);
            const ull wii = pack2(wi, wi);
            #pragma unroll
            for (int o = 0; o < OPT; o++) {
                ffma2(accA[o], xw[k + o], wrr);
                ffma2(accB[o], xw[k + o], wii);
            }
        }
    }

    // ---- post-stage MLP (relu) + rotation + store ----
    float cw1p[8], cb1p[8], cw2p[8];
    #pragma unroll
    for (int f = 0; f < 8; f++) { cw1p[f] = sw1p[f]; cb1p[f] = sb1p[f]; cw2p[f] = sw2p[f]; }
    const float cb2 = sb2;

    const int obase = t0 + tid * OPT;
    float2* orow = out + (size_t)b * WOUT + obase;
    #pragma unroll
    for (int o = 0; o < OPT; o++) {
        if (obase + o < WOUT) {
            float alo, ahi, blo, bhi;
            unpack2(accA[o], alo, ahi);
            unpack2(accB[o], blo, bhi);
            const float zr = alo - bhi;   // Σ xr·wr − Σ xi·wi
            const float zi = ahi + blo;   // Σ xi·wr + Σ xr·wi
            float s    = fmaf(zr, zr, zi * zi);
            float inv  = (s > 0.0f) ? rsqrtf(s) : 0.0f;
            float zmag = s * inv;
            float cosz = (s > 0.0f) ? zr * inv : 1.0f;
            float sinz = zi * inv;
            float zm = cb2;
            #pragma unroll
            for (int f = 0; f < 8; f++) {
                float g = fmaf(zmag, cw1p[f], cb1p[f]);
                g = fmaxf(g, 0.0f);
                zm = fmaf(g, cw2p[f], zm);
            }
            orow[o] = make_float2(SCALEF * zm * cosz, SCALEF * zm * sinz);
        }
    }
}

extern "C" void kernel_launch(void* const* d_in, const int* in_sizes, int n_in,
                              void* d_out, int out_size)
{
    (void)in_sizes; (void)n_in; (void)out_size;
    const float* xr   = (const float*)d_in[0];
    const float* xi   = (const float*)d_in[1];
    const float* w1pr = (const float*)d_in[2];
    const float* w2pr = (const float*)d_in[3];
    const float* wfr  = (const float*)d_in[4];
    const float* wfi  = (const float*)d_in[5];
    const float* w1po = (const float*)d_in[6];
    const float* b1po = (const float*)d_in[7];
    const float* w2po = (const float*)d_in[8];
    const float* b2po = (const float*)d_in[9];

    dim3 grid(NTILES, BATCH);
    hammer_wiener_kernel<<<grid, TPB>>>(xr, xi, w1pr, w2pr, wfr, wfi,
                                        w1po, b1po, w2po, b2po,
                                        (float2*)d_out);
}